// round 8
// baseline (speedup 1.0000x reference)
#include <cuda_runtime.h>
#include <cuda_fp16.h>
#include <cstdint>

// ============================================================================
// Problem constants
// ============================================================================
#define OUT_F   16384
#define IN_F    4096
#define M_TOK   8192            // 4 * 2048 tokens
#define NGROUPS 4194304         // OUT_F*IN_F/16

// GEMM tiling (warp-level HMMA; PTX target is plain sm_100 -> no tcgen05)
#define BM 256
#define BN 128
#define BK 64
#define STAGES 4
#define KTILES (IN_F / BK)      // 64

#define A_TILE 32768            // 256 rows x 128B (64 fp16)
#define B_TILE 16384            // 128 rows x 128B
#define STAGE_BYTES (A_TILE + B_TILE)   // 49152

// SMEM layout (dynamic):
//   [16:80)  full[s]/empty[s] mbarriers, 16B per stage (full at +0, empty at +8)
//   [4096..) pipeline stages (stage bases 1024-aligned)
#define SM_BARS   16
#define SM_TILES  4096
#define SMEM_TOTAL (SM_TILES + STAGES * STAGE_BYTES)   // 200704

// ============================================================================
// Persistent scratch: pre-dequantized, pre-tiled, pre-SW128-swizzled operands,
// laid out exactly as the GEMM's SMEM stages expect -> one bulk copy per tile.
//  A: tile (mt 256-rows, kt) at ((mt*KTILES)+kt)*32768; interior r*128+c*2, SW128
//  W: tile (nt 128-rows, kt) at ((nt*KTILES)+kt)*16384; interior r*128+c*2, SW128
// ============================================================================
__device__ __align__(1024) static unsigned char g_Wtil[(size_t)OUT_F * IN_F * 2]; // 128 MB
__device__ __align__(1024) static unsigned char g_Atil[(size_t)M_TOK * IN_F * 2]; //  64 MB

// ============================================================================
// PTX helpers (sm_90-level only: mbarrier, cp.async.bulk, ldmatrix, mma.sync)
// ============================================================================
__device__ __forceinline__ uint32_t smem_u32(const void* p) {
    uint32_t a;
    asm("{ .reg .u64 t; cvta.to.shared.u64 t, %1; cvt.u32.u64 %0, t; }" : "=r"(a) : "l"(p));
    return a;
}

__device__ __forceinline__ uint32_t elect_one() {
    uint32_t pred;
    asm volatile("{\n\t.reg .pred p;\n\telect.sync _|p, 0xFFFFFFFF;\n\t"
                 "selp.b32 %0, 1, 0, p;\n\t}" : "=r"(pred));
    return pred;
}

__device__ __forceinline__ uint32_t swz(uint32_t off) {   // SW128: bits[6:4] ^= bits[9:7]
    return off ^ ((off >> 3) & 0x70);
}

#define MBAR_INIT(addr, cnt) \
    asm volatile("mbarrier.init.shared.b64 [%0], %1;" :: "r"(addr), "r"(cnt) : "memory")

#define MBAR_ARRIVE(addr) \
    asm volatile("mbarrier.arrive.shared.b64 _, [%0];" :: "r"(addr) : "memory")

#define MBAR_EXPECT_TX(addr, bytes) \
    asm volatile("mbarrier.arrive.expect_tx.shared.b64 _, [%0], %1;" :: "r"(addr), "r"(bytes) : "memory")

#define MBAR_WAIT(addr, ph) do {                                                    \
    uint32_t _m = (addr), _p = (ph), _d;                                            \
    asm volatile("{\n\t.reg .pred p;\n\t"                                           \
        "mbarrier.try_wait.parity.acquire.cta.shared::cta.b64 p, [%1], %2;\n\t"     \
        "selp.b32 %0, 1, 0, p;\n\t}" : "=r"(_d) : "r"(_m), "r"(_p) : "memory");     \
    if (!_d) {                                                                      \
        asm volatile("{\n\t.reg .pred P1;\n\t"                                      \
            "WL_%=:\n\t"                                                            \
            "mbarrier.try_wait.parity.acquire.cta.shared::cta.b64 P1, [%0], %1, 0x989680;\n\t" \
            "@P1 bra.uni WD_%=;\n\t"                                                \
            "bra.uni WL_%=;\n\t"                                                    \
            "WD_%=:\n\t}" :: "r"(_m), "r"(_p) : "memory");                          \
    }                                                                               \
} while (0)

#define MBAR_WAIT_RELAXED(addr, ph) do {                                            \
    uint32_t _m = (addr), _p = (ph), _d;                                            \
    asm volatile("{\n\t.reg .pred p;\n\t"                                           \
        "mbarrier.try_wait.parity.relaxed.cta.shared::cta.b64 p, [%1], %2, 0x989680;\n\t" \
        "selp.b32 %0, 1, 0, p;\n\t}" : "=r"(_d) : "r"(_m), "r"(_p) : "memory");     \
    if (!_d) {                                                                      \
        asm volatile("{\n\t.reg .pred P1;\n\t"                                      \
            "WL_%=:\n\t"                                                            \
            "mbarrier.try_wait.parity.relaxed.cta.shared::cta.b64 P1, [%0], %1, 0x989680;\n\t" \
            "@P1 bra.uni WD_%=;\n\t"                                                \
            "bra.uni WL_%=;\n\t"                                                    \
            "WD_%=:\n\t}" :: "r"(_m), "r"(_p) : "memory");                          \
    }                                                                               \
} while (0)

__device__ __forceinline__ void bulk_g2s(uint32_t dst, const void* src, uint32_t bytes, uint32_t mbar) {
    asm volatile(
        "cp.async.bulk.shared::cluster.global.mbarrier::complete_tx::bytes [%0], [%1], %2, [%3];"
        :: "r"(dst), "l"(src), "r"(bytes), "r"(mbar) : "memory");
}

#define LDSM4(r0, r1, r2, r3, addr) \
    asm volatile("ldmatrix.sync.aligned.m8n8.x4.shared.b16 {%0,%1,%2,%3}, [%4];" \
        : "=r"(r0), "=r"(r1), "=r"(r2), "=r"(r3) : "r"(addr))

// fp16-accumulator HMMA: D(f16x2 x2) = A*B + D.  2x the f32-accum rate.
__device__ __forceinline__ void mma_f16acc(uint32_t* d, uint32_t a0, uint32_t a1,
                                           uint32_t a2, uint32_t a3,
                                           uint32_t b0, uint32_t b1) {
    asm volatile(
        "mma.sync.aligned.m16n8k16.row.col.f16.f16.f16.f16 "
        "{%0,%1}, {%2,%3,%4,%5}, {%6,%7}, {%0,%1};"
        : "+r"(d[0]), "+r"(d[1])
        : "r"(a0), "r"(a1), "r"(a2), "r"(a3), "r"(b0), "r"(b1));
}

// Chunk-start variant: C = 0 (skips explicit zero-init of the f16 accumulators)
__device__ __forceinline__ void mma_f16zero(uint32_t* d, uint32_t a0, uint32_t a1,
                                            uint32_t a2, uint32_t a3,
                                            uint32_t b0, uint32_t b1) {
    asm volatile(
        "mma.sync.aligned.m16n8k16.row.col.f16.f16.f16.f16 "
        "{%0,%1}, {%2,%3,%4,%5}, {%6,%7}, {%8,%8};"
        : "=r"(d[0]), "=r"(d[1])
        : "r"(a0), "r"(a1), "r"(a2), "r"(a3), "r"(b0), "r"(b1), "r"(0u));
}

// ============================================================================
// Kernel 1 (fused prep): blocks [0,16384) dequantize W, [16384,32768) convert A.
// Fusing keeps 2 launches per replay so ncu's "-s 5 -c 1" lands on the GEMM.
// ============================================================================
__global__ void __launch_bounds__(256) prep_kernel(const int* __restrict__ q,
                                                   const float* __restrict__ nrm,
                                                   const float* __restrict__ x) {
    if (blockIdx.x < 16384) {
        // ---- dequant: group g -> W row o=g/256, cols (g%256)*16..+15 ----
        int g = blockIdx.x * 256 + threadIdx.x;   // 0 .. NGROUPS-1
        const int4* qp = (const int4*)(q + (size_t)g * 8);
        int4 q0 = qp[0];
        int4 q1 = qp[1];
        float nv = nrm[g];
        float s = nv * (2.0f / 15.0f);

        int o  = g >> 8;          // output row 0..16383
        int k0 = (g & 255) * 16;  // starting K column

        int nt = o >> 7;          // 128-row N tile
        int r  = o & 127;
        int kt = k0 >> 6;
        int cc = k0 & 63;

        size_t tile_base = (size_t)(nt * KTILES + kt) * (size_t)B_TILE;
        uint32_t off = (uint32_t)r * 128u + (uint32_t)cc * 2u;   // 32B aligned
        uint32_t sw0 = swz(off);
        uint32_t sw1 = swz(off + 16u);

        __align__(16) __half h[16];
        int b[8] = {q0.x, q0.y, q0.z, q0.w, q1.x, q1.y, q1.z, q1.w};
#pragma unroll
        for (int j = 0; j < 8; j++) {
            int lo = b[j] & 15;
            int hi = (b[j] >> 4) & 15;
            h[2 * j]     = __float2half_rn((float)lo * s - nv);
            h[2 * j + 1] = __float2half_rn((float)hi * s - nv);
        }
        *(uint4*)(g_Wtil + tile_base + sw0) = *(const uint4*)&h[0];
        *(uint4*)(g_Wtil + tile_base + sw1) = *(const uint4*)&h[8];
    } else {
        // ---- aconv: fp32 -> fp16, 256-row tiles, SW128 ----
        int t = (blockIdx.x - 16384) * 256 + threadIdx.x;   // 0 .. M_TOK*IN_F/8-1
        int m  = t >> 9;                  // 512 8-elt chunks per row
        int kc = (t & 511) * 8;

        const float4* xp = (const float4*)(x + (size_t)m * IN_F + kc);
        float4 x0 = xp[0];
        float4 x1 = xp[1];
        __align__(16) __half h[8];
        h[0] = __float2half_rn(x0.x); h[1] = __float2half_rn(x0.y);
        h[2] = __float2half_rn(x0.z); h[3] = __float2half_rn(x0.w);
        h[4] = __float2half_rn(x1.x); h[5] = __float2half_rn(x1.y);
        h[6] = __float2half_rn(x1.z); h[7] = __float2half_rn(x1.w);

        int mt = m >> 8;          // 256-row tile
        int r  = m & 255;
        int kt = kc >> 6;
        int c0 = kc & 63;
        size_t tile_base = (size_t)(mt * KTILES + kt) * (size_t)A_TILE;
        uint32_t off = (uint32_t)r * 128u + (uint32_t)c0 * 2u;   // 16B aligned
        *(uint4*)(g_Atil + tile_base + swz(off)) = *(const uint4*)h;
    }
}

// ============================================================================
// Kernel 2: pipelined warp-MMA fp16 GEMM, two-level accumulation:
//   fp16 accumulators within one BK=64 chunk (4 HMMA), promoted to fp32
//   masters once per chunk. f16-accum HMMA runs at 2x the f32-accum rate.
//   grid = 32 (mt, fastest) x 128 (nt) = 4096 CTAs, 288 threads:
//     warps 0-7: compute, 4x2 grid, 64x64 tile each
//     warp 8:    producer (cp.async.bulk A 32KB + B 16KB per stage)
// ============================================================================
__global__ void __launch_bounds__(288, 1) gemm_kernel(const float* __restrict__ bias,
                                                      float* __restrict__ out) {
    extern __shared__ unsigned char smem[];
    uint32_t sb = smem_u32(smem);
    int tid = threadIdx.x;
    int wid = tid >> 5;
    int lane = tid & 31;

    int mt = blockIdx.x & 31;   // M fastest: whole wave shares B band; A stays L2-hot
    int nt = blockIdx.x >> 5;

    if (tid == 0) {
#pragma unroll
        for (int s = 0; s < STAGES; s++) {
            MBAR_INIT(sb + SM_BARS + s * 16, 1);      // full: producer expect_tx
            MBAR_INIT(sb + SM_BARS + s * 16 + 8, 8);  // empty: 8 compute-warp arrivals
        }
    }
    __syncthreads();

    if (wid == 8) {
        // ------------------------- producer -------------------------
        if (elect_one()) {
            int phase = 1;  // first STAGES empty-waits pass immediately
            const unsigned char* aSrc = g_Atil + (size_t)(mt * KTILES) * (size_t)A_TILE;
            const unsigned char* bSrc = g_Wtil + (size_t)(nt * KTILES) * (size_t)B_TILE;
            for (int kt = 0; kt < KTILES; kt++) {
                int s = kt & (STAGES - 1);
                uint32_t full  = sb + SM_BARS + s * 16;
                uint32_t empty = full + 8;
                MBAR_WAIT_RELAXED(empty, phase);
                MBAR_EXPECT_TX(full, STAGE_BYTES);
                uint32_t dst = sb + SM_TILES + s * STAGE_BYTES;
                bulk_g2s(dst, aSrc + (size_t)kt * A_TILE, A_TILE, full);
                bulk_g2s(dst + A_TILE, bSrc + (size_t)kt * B_TILE, B_TILE, full);
                if (s == STAGES - 1) phase ^= 1;
            }
        }
        return;
    }

    // ------------------------- compute warps -------------------------
    int wm = wid >> 1;          // 0..3 -> 64-row band
    int wn = wid & 1;           // 0..1 -> 64-col band

    float acc[4][8][4];         // fp32 masters
#pragma unroll
    for (int mi = 0; mi < 4; mi++)
#pragma unroll
        for (int nj = 0; nj < 8; nj++)
#pragma unroll
            for (int k = 0; k < 4; k++) acc[mi][nj][k] = 0.0f;

    // ldmatrix per-thread address components (SW128-swizzled 128B rows)
    uint32_t arow = (uint32_t)(wm * 64) + (lane & 15);
    uint32_t acol = (uint32_t)((lane >> 4) << 4);                 // 0 / 16 bytes
    uint32_t brow = (uint32_t)(wn * 64) + (lane & 7) + (uint32_t)((lane >> 4) << 3);
    uint32_t bcol = (uint32_t)(((lane >> 3) & 1) << 4);           // 0 / 16 bytes

    int phase = 0;
    for (int kt = 0; kt < KTILES; kt++) {
        int s = kt & (STAGES - 1);
        uint32_t full  = sb + SM_BARS + s * 16;
        uint32_t empty = full + 8;
        MBAR_WAIT(full, phase);
        uint32_t aB = sb + SM_TILES + s * STAGE_BYTES;
        uint32_t bB = aB + A_TILE;

        uint32_t facc[4][8][2];                      // fp16 chunk accumulators
#pragma unroll
        for (int ks = 0; ks < 4; ks++) {             // BK=64 / 16 = one chunk
            uint32_t a[4][4];
            uint32_t b[8][2];
#pragma unroll
            for (int mi = 0; mi < 4; mi++) {
                uint32_t off = (arow + mi * 16) * 128u + (uint32_t)(ks * 32) + acol;
                LDSM4(a[mi][0], a[mi][1], a[mi][2], a[mi][3], aB + swz(off));
            }
#pragma unroll
            for (int nj2 = 0; nj2 < 4; nj2++) {
                uint32_t off = (brow + nj2 * 16) * 128u + (uint32_t)(ks * 32) + bcol;
                LDSM4(b[2 * nj2][0], b[2 * nj2][1], b[2 * nj2 + 1][0], b[2 * nj2 + 1][1],
                      bB + swz(off));
            }
            if (ks == 0) {
#pragma unroll
                for (int mi = 0; mi < 4; mi++)
#pragma unroll
                    for (int nj = 0; nj < 8; nj++)
                        mma_f16zero(facc[mi][nj], a[mi][0], a[mi][1], a[mi][2], a[mi][3],
                                    b[nj][0], b[nj][1]);
            } else {
#pragma unroll
                for (int mi = 0; mi < 4; mi++)
#pragma unroll
                    for (int nj = 0; nj < 8; nj++)
                        mma_f16acc(facc[mi][nj], a[mi][0], a[mi][1], a[mi][2], a[mi][3],
                                   b[nj][0], b[nj][1]);
            }
        }

        // promote chunk (fp16) into fp32 masters
#pragma unroll
        for (int mi = 0; mi < 4; mi++)
#pragma unroll
            for (int nj = 0; nj < 8; nj++) {
                float2 f0 = __half22float2(*(const __half2*)&facc[mi][nj][0]);
                float2 f1 = __half22float2(*(const __half2*)&facc[mi][nj][1]);
                acc[mi][nj][0] += f0.x;
                acc[mi][nj][1] += f0.y;
                acc[mi][nj][2] += f1.x;
                acc[mi][nj][3] += f1.y;
            }

        if (lane == 0) MBAR_ARRIVE(empty);
        if (s == STAGES - 1) phase ^= 1;
    }

    // ------------------------- epilogue: +bias, STG.64 -------------------------
    {
        int colbase = nt * BN + wn * 64 + (lane & 3) * 2;
        const float* bb = bias + colbase;
        float2 bv[8];
#pragma unroll
        for (int nj = 0; nj < 8; nj++) bv[nj] = *(const float2*)(bb + nj * 8);

        int rbase = mt * BM + wm * 64 + (lane >> 2);
#pragma unroll
        for (int mi = 0; mi < 4; mi++) {
            float* p0 = out + (size_t)(rbase + mi * 16) * OUT_F + colbase;
            float* p1 = p0 + (size_t)8 * OUT_F;
#pragma unroll
            for (int nj = 0; nj < 8; nj++) {
                float2 v0 = {acc[mi][nj][0] + bv[nj].x, acc[mi][nj][1] + bv[nj].y};
                float2 v1 = {acc[mi][nj][2] + bv[nj].x, acc[mi][nj][3] + bv[nj].y};
                *(float2*)(p0 + nj * 8) = v0;
                *(float2*)(p1 + nj * 8) = v1;
            }
        }
    }
}

// ============================================================================
// Launch
// ============================================================================
extern "C" void kernel_launch(void* const* d_in, const int* in_sizes, int n_in,
                              void* d_out, int out_size) {
    const float* x    = (const float*)d_in[0];   // [4,2048,4096] fp32
    const int*   q    = (const int*)d_in[1];     // [4194304, 8] int32 (one byte each)
    const float* nrm  = (const float*)d_in[2];   // [4194304, 1] fp32
    const float* bias = (const float*)d_in[3];   // [16384] fp32
    float* out = (float*)d_out;                  // [4,2048,16384] fp32

    cudaFuncSetAttribute(gemm_kernel, cudaFuncAttributeMaxDynamicSharedMemorySize, SMEM_TOTAL);

    prep_kernel<<<32768, 256>>>(q, nrm, x);
    gemm_kernel<<<32 * 128, 288, SMEM_TOTAL>>>(bias, out);
}

// round 10
// speedup vs baseline: 1.5619x; 1.5619x over previous
#include <cuda_runtime.h>
#include <cuda_fp16.h>
#include <cstdint>

// ============================================================================
// Problem constants
// ============================================================================
#define OUT_F   16384
#define IN_F    4096
#define M_TOK   8192            // 4 * 2048 tokens
#define NGROUPS 4194304         // OUT_F*IN_F/16

// GEMM tiling (warp-level HMMA; PTX target is plain sm_100 -> no tcgen05)
#define BM 256
#define BN 128
#define BK 64
#define STAGES 4
#define KTILES (IN_F / BK)      // 64

#define A_TILE 32768            // 256 rows x 128B (64 fp16)
#define B_TILE 16384            // 128 rows x 128B
#define STAGE_BYTES (A_TILE + B_TILE)   // 49152

// SMEM layout (dynamic):
//   [16:80)  full[s]/empty[s] mbarriers, 16B per stage (full at +0, empty at +8)
//   [4096..) pipeline stages (stage bases 1024-aligned)
#define SM_BARS   16
#define SM_TILES  4096
#define SMEM_TOTAL (SM_TILES + STAGES * STAGE_BYTES)   // 200704

#define NWARPS_C 16             // compute warps (32x64 tile each)
#define NTHREADS (NWARPS_C * 32 + 32)   // 544: 16 compute + 1 producer warp

// ============================================================================
// Persistent scratch: pre-dequantized, pre-tiled, pre-SW128-swizzled operands,
// laid out exactly as the GEMM's SMEM stages expect -> one bulk copy per tile.
//  A: tile (mt 256-rows, kt) at ((mt*KTILES)+kt)*32768; interior r*128+c*2, SW128
//  W: tile (nt 128-rows, kt) at ((nt*KTILES)+kt)*16384; interior r*128+c*2, SW128
// ============================================================================
__device__ __align__(1024) static unsigned char g_Wtil[(size_t)OUT_F * IN_F * 2]; // 128 MB
__device__ __align__(1024) static unsigned char g_Atil[(size_t)M_TOK * IN_F * 2]; //  64 MB

// ============================================================================
// PTX helpers (sm_90-level only: mbarrier, cp.async.bulk, ldmatrix, mma.sync)
// ============================================================================
__device__ __forceinline__ uint32_t smem_u32(const void* p) {
    uint32_t a;
    asm("{ .reg .u64 t; cvta.to.shared.u64 t, %1; cvt.u32.u64 %0, t; }" : "=r"(a) : "l"(p));
    return a;
}

__device__ __forceinline__ uint32_t elect_one() {
    uint32_t pred;
    asm volatile("{\n\t.reg .pred p;\n\telect.sync _|p, 0xFFFFFFFF;\n\t"
                 "selp.b32 %0, 1, 0, p;\n\t}" : "=r"(pred));
    return pred;
}

__device__ __forceinline__ uint32_t swz(uint32_t off) {   // SW128: bits[6:4] ^= bits[9:7]
    return off ^ ((off >> 3) & 0x70);
}

#define MBAR_INIT(addr, cnt) \
    asm volatile("mbarrier.init.shared.b64 [%0], %1;" :: "r"(addr), "r"(cnt) : "memory")

#define MBAR_ARRIVE(addr) \
    asm volatile("mbarrier.arrive.shared.b64 _, [%0];" :: "r"(addr) : "memory")

#define MBAR_EXPECT_TX(addr, bytes) \
    asm volatile("mbarrier.arrive.expect_tx.shared.b64 _, [%0], %1;" :: "r"(addr), "r"(bytes) : "memory")

#define MBAR_WAIT(addr, ph) do {                                                    \
    uint32_t _m = (addr), _p = (ph), _d;                                            \
    asm volatile("{\n\t.reg .pred p;\n\t"                                           \
        "mbarrier.try_wait.parity.acquire.cta.shared::cta.b64 p, [%1], %2;\n\t"     \
        "selp.b32 %0, 1, 0, p;\n\t}" : "=r"(_d) : "r"(_m), "r"(_p) : "memory");     \
    if (!_d) {                                                                      \
        asm volatile("{\n\t.reg .pred P1;\n\t"                                      \
            "WL_%=:\n\t"                                                            \
            "mbarrier.try_wait.parity.acquire.cta.shared::cta.b64 P1, [%0], %1, 0x989680;\n\t" \
            "@P1 bra.uni WD_%=;\n\t"                                                \
            "bra.uni WL_%=;\n\t"                                                    \
            "WD_%=:\n\t}" :: "r"(_m), "r"(_p) : "memory");                          \
    }                                                                               \
} while (0)

#define MBAR_WAIT_RELAXED(addr, ph) do {                                            \
    uint32_t _m = (addr), _p = (ph), _d;                                            \
    asm volatile("{\n\t.reg .pred p;\n\t"                                           \
        "mbarrier.try_wait.parity.relaxed.cta.shared::cta.b64 p, [%1], %2, 0x989680;\n\t" \
        "selp.b32 %0, 1, 0, p;\n\t}" : "=r"(_d) : "r"(_m), "r"(_p) : "memory");     \
    if (!_d) {                                                                      \
        asm volatile("{\n\t.reg .pred P1;\n\t"                                      \
            "WL_%=:\n\t"                                                            \
            "mbarrier.try_wait.parity.relaxed.cta.shared::cta.b64 P1, [%0], %1, 0x989680;\n\t" \
            "@P1 bra.uni WD_%=;\n\t"                                                \
            "bra.uni WL_%=;\n\t"                                                    \
            "WD_%=:\n\t}" :: "r"(_m), "r"(_p) : "memory");                          \
    }                                                                               \
} while (0)

__device__ __forceinline__ void bulk_g2s(uint32_t dst, const void* src, uint32_t bytes, uint32_t mbar) {
    asm volatile(
        "cp.async.bulk.shared::cluster.global.mbarrier::complete_tx::bytes [%0], [%1], %2, [%3];"
        :: "r"(dst), "l"(src), "r"(bytes), "r"(mbar) : "memory");
}

#define LDSM4(r0, r1, r2, r3, addr) \
    asm volatile("ldmatrix.sync.aligned.m8n8.x4.shared.b16 {%0,%1,%2,%3}, [%4];" \
        : "=r"(r0), "=r"(r1), "=r"(r2), "=r"(r3) : "r"(addr))

__device__ __forceinline__ void mma16816(float* c, uint32_t a0, uint32_t a1, uint32_t a2,
                                         uint32_t a3, uint32_t b0, uint32_t b1) {
    asm volatile(
        "mma.sync.aligned.m16n8k16.row.col.f32.f16.f16.f32 "
        "{%0,%1,%2,%3}, {%4,%5,%6,%7}, {%8,%9}, {%0,%1,%2,%3};"
        : "+f"(c[0]), "+f"(c[1]), "+f"(c[2]), "+f"(c[3])
        : "r"(a0), "r"(a1), "r"(a2), "r"(a3), "r"(b0), "r"(b1));
}

// ============================================================================
// Kernel 1 (fused prep): blocks [0,16384) dequantize W, [16384,32768) convert A.
// Fusing keeps 2 launches per replay so ncu's "-s 5 -c 1" lands on the GEMM.
// ============================================================================
__global__ void __launch_bounds__(256) prep_kernel(const int* __restrict__ q,
                                                   const float* __restrict__ nrm,
                                                   const float* __restrict__ x) {
    if (blockIdx.x < 16384) {
        // ---- dequant: group g -> W row o=g/256, cols (g%256)*16..+15 ----
        int g = blockIdx.x * 256 + threadIdx.x;   // 0 .. NGROUPS-1
        const int4* qp = (const int4*)(q + (size_t)g * 8);
        int4 q0 = qp[0];
        int4 q1 = qp[1];
        float nv = nrm[g];
        float s = nv * (2.0f / 15.0f);

        int o  = g >> 8;          // output row 0..16383
        int k0 = (g & 255) * 16;  // starting K column

        int nt = o >> 7;          // 128-row N tile
        int r  = o & 127;
        int kt = k0 >> 6;
        int cc = k0 & 63;

        size_t tile_base = (size_t)(nt * KTILES + kt) * (size_t)B_TILE;
        uint32_t off = (uint32_t)r * 128u + (uint32_t)cc * 2u;   // 32B aligned
        uint32_t sw0 = swz(off);
        uint32_t sw1 = swz(off + 16u);

        __align__(16) __half h[16];
        int b[8] = {q0.x, q0.y, q0.z, q0.w, q1.x, q1.y, q1.z, q1.w};
#pragma unroll
        for (int j = 0; j < 8; j++) {
            int lo = b[j] & 15;
            int hi = (b[j] >> 4) & 15;
            h[2 * j]     = __float2half_rn((float)lo * s - nv);
            h[2 * j + 1] = __float2half_rn((float)hi * s - nv);
        }
        *(uint4*)(g_Wtil + tile_base + sw0) = *(const uint4*)&h[0];
        *(uint4*)(g_Wtil + tile_base + sw1) = *(const uint4*)&h[8];
    } else {
        // ---- aconv: fp32 -> fp16, 256-row tiles, SW128 ----
        int t = (blockIdx.x - 16384) * 256 + threadIdx.x;   // 0 .. M_TOK*IN_F/8-1
        int m  = t >> 9;                  // 512 8-elt chunks per row
        int kc = (t & 511) * 8;

        const float4* xp = (const float4*)(x + (size_t)m * IN_F + kc);
        float4 x0 = xp[0];
        float4 x1 = xp[1];
        __align__(16) __half h[8];
        h[0] = __float2half_rn(x0.x); h[1] = __float2half_rn(x0.y);
        h[2] = __float2half_rn(x0.z); h[3] = __float2half_rn(x0.w);
        h[4] = __float2half_rn(x1.x); h[5] = __float2half_rn(x1.y);
        h[6] = __float2half_rn(x1.z); h[7] = __float2half_rn(x1.w);

        int mt = m >> 8;          // 256-row tile
        int r  = m & 255;
        int kt = kc >> 6;
        int c0 = kc & 63;
        size_t tile_base = (size_t)(mt * KTILES + kt) * (size_t)A_TILE;
        uint32_t off = (uint32_t)r * 128u + (uint32_t)c0 * 2u;   // 16B aligned
        *(uint4*)(g_Atil + tile_base + swz(off)) = *(const uint4*)h;
    }
}

// ============================================================================
// Kernel 2: pipelined warp-MMA fp16 GEMM (f32 accum, HMMA rt8/SMSP).
//   R8 showed the binder is issue/occupancy (2 compute warps/SMSP, issue 30%),
//   not the tensor pipe (44%). This round: 16 compute warps of 32x64 each
//   (4.25 warps/SMSP) to cover LDSM latency; f32 accum (f16-accum promote tax
//   was 0.7ms for zero tensor gain -- same rt both widths on this chip).
//   grid = 32 (mt, fastest) x 128 (nt) = 4096 CTAs, 544 threads:
//     warps 0-15: compute, 8x2 grid, 32x64 tile each
//     warp 16:    producer (cp.async.bulk A 32KB + B 16KB per stage)
// ============================================================================
__global__ void __launch_bounds__(NTHREADS, 1) gemm_kernel(const float* __restrict__ bias,
                                                           float* __restrict__ out) {
    extern __shared__ unsigned char smem[];
    uint32_t sb = smem_u32(smem);
    int tid = threadIdx.x;
    int wid = tid >> 5;
    int lane = tid & 31;

    int mt = blockIdx.x & 31;   // M fastest: whole wave shares B band; A stays L2-hot
    int nt = blockIdx.x >> 5;

    if (tid == 0) {
#pragma unroll
        for (int s = 0; s < STAGES; s++) {
            MBAR_INIT(sb + SM_BARS + s * 16, 1);             // full: producer expect_tx
            MBAR_INIT(sb + SM_BARS + s * 16 + 8, NWARPS_C);  // empty: compute arrivals
        }
    }
    __syncthreads();

    if (wid == NWARPS_C) {
        // ------------------------- producer -------------------------
        if (elect_one()) {
            int phase = 1;  // first STAGES empty-waits pass immediately
            const unsigned char* aSrc = g_Atil + (size_t)(mt * KTILES) * (size_t)A_TILE;
            const unsigned char* bSrc = g_Wtil + (size_t)(nt * KTILES) * (size_t)B_TILE;
            for (int kt = 0; kt < KTILES; kt++) {
                int s = kt & (STAGES - 1);
                uint32_t full  = sb + SM_BARS + s * 16;
                uint32_t empty = full + 8;
                MBAR_WAIT_RELAXED(empty, phase);
                MBAR_EXPECT_TX(full, STAGE_BYTES);
                uint32_t dst = sb + SM_TILES + s * STAGE_BYTES;
                bulk_g2s(dst, aSrc + (size_t)kt * A_TILE, A_TILE, full);
                bulk_g2s(dst + A_TILE, bSrc + (size_t)kt * B_TILE, B_TILE, full);
                if (s == STAGES - 1) phase ^= 1;
            }
        }
        return;
    }

    // ------------------------- compute warps -------------------------
    int wm = wid >> 1;          // 0..7 -> 32-row band
    int wn = wid & 1;           // 0..1 -> 64-col band

    float acc[2][8][4];
#pragma unroll
    for (int mi = 0; mi < 2; mi++)
#pragma unroll
        for (int nj = 0; nj < 8; nj++)
#pragma unroll
            for (int k = 0; k < 4; k++) acc[mi][nj][k] = 0.0f;

    // ldmatrix per-thread address components (SW128-swizzled 128B rows)
    uint32_t arow = (uint32_t)(wm * 32) + (lane & 15);
    uint32_t acol = (uint32_t)((lane >> 4) << 4);                 // 0 / 16 bytes
    uint32_t brow = (uint32_t)(wn * 64) + (lane & 7) + (uint32_t)((lane >> 4) << 3);
    uint32_t bcol = (uint32_t)(((lane >> 3) & 1) << 4);           // 0 / 16 bytes

    int phase = 0;
    for (int kt = 0; kt < KTILES; kt++) {
        int s = kt & (STAGES - 1);
        uint32_t full  = sb + SM_BARS + s * 16;
        uint32_t empty = full + 8;
        MBAR_WAIT(full, phase);
        uint32_t aB = sb + SM_TILES + s * STAGE_BYTES;
        uint32_t bB = aB + A_TILE;

#pragma unroll
        for (int ks = 0; ks < 4; ks++) {             // BK=64 / 16
            uint32_t a[2][4];
            uint32_t b[8][2];
#pragma unroll
            for (int mi = 0; mi < 2; mi++) {
                uint32_t off = (arow + mi * 16) * 128u + (uint32_t)(ks * 32) + acol;
                LDSM4(a[mi][0], a[mi][1], a[mi][2], a[mi][3], aB + swz(off));
            }
#pragma unroll
            for (int nj2 = 0; nj2 < 4; nj2++) {
                uint32_t off = (brow + nj2 * 16) * 128u + (uint32_t)(ks * 32) + bcol;
                LDSM4(b[2 * nj2][0], b[2 * nj2][1], b[2 * nj2 + 1][0], b[2 * nj2 + 1][1],
                      bB + swz(off));
            }
#pragma unroll
            for (int mi = 0; mi < 2; mi++)
#pragma unroll
                for (int nj = 0; nj < 8; nj++)
                    mma16816(acc[mi][nj], a[mi][0], a[mi][1], a[mi][2], a[mi][3],
                             b[nj][0], b[nj][1]);
        }

        if (lane == 0) MBAR_ARRIVE(empty);
        if (s == STAGES - 1) phase ^= 1;
    }

    // ------------------------- epilogue: +bias, STG.64 -------------------------
    {
        int colbase = nt * BN + wn * 64 + (lane & 3) * 2;
        const float* bb = bias + colbase;
        float2 bv[8];
#pragma unroll
        for (int nj = 0; nj < 8; nj++) bv[nj] = *(const float2*)(bb + nj * 8);

        int rbase = mt * BM + wm * 32 + (lane >> 2);
#pragma unroll
        for (int mi = 0; mi < 2; mi++) {
            float* p0 = out + (size_t)(rbase + mi * 16) * OUT_F + colbase;
            float* p1 = p0 + (size_t)8 * OUT_F;
#pragma unroll
            for (int nj = 0; nj < 8; nj++) {
                float2 v0 = {acc[mi][nj][0] + bv[nj].x, acc[mi][nj][1] + bv[nj].y};
                float2 v1 = {acc[mi][nj][2] + bv[nj].x, acc[mi][nj][3] + bv[nj].y};
                *(float2*)(p0 + nj * 8) = v0;
                *(float2*)(p1 + nj * 8) = v1;
            }
        }
    }
}

// ============================================================================
// Launch
// ============================================================================
extern "C" void kernel_launch(void* const* d_in, const int* in_sizes, int n_in,
                              void* d_out, int out_size) {
    const float* x    = (const float*)d_in[0];   // [4,2048,4096] fp32
    const int*   q    = (const int*)d_in[1];     // [4194304, 8] int32 (one byte each)
    const float* nrm  = (const float*)d_in[2];   // [4194304, 1] fp32
    const float* bias = (const float*)d_in[3];   // [16384] fp32
    float* out = (float*)d_out;                  // [4,2048,16384] fp32

    cudaFuncSetAttribute(gemm_kernel, cudaFuncAttributeMaxDynamicSharedMemorySize, SMEM_TOTAL);

    prep_kernel<<<32768, 256>>>(q, nrm, x);
    gemm_kernel<<<32 * 128, NTHREADS, SMEM_TOTAL>>>(bias, out);
}